// round 16
// baseline (speedup 1.0000x reference)
#include <cuda_runtime.h>
#include <cuda_fp16.h>
#include <cstdint>

#define BSZ   16
#define NN    1024
#define HIDD  64
#define DD    128
#define CC    256
#define PREK  4
#define NSPLIT 16

#define XSZ   (BSZ * NN * CC)
#define OUT0  (BSZ * NN * DD)

#define PHASE_SCALE ((float)(3.141592653589793 / 0.21875))

// ===================== base-ISA tensor helpers (sm_80+) =====================
__device__ __forceinline__ uint32_t smem_to_u32(const void* p) {
    uint32_t a;
    asm("{ .reg .u64 t; cvta.to.shared.u64 t, %1; cvt.u32.u64 %0, t; }" : "=r"(a) : "l"(p));
    return a;
}
__device__ __forceinline__ void ldmx4(uint32_t* r, uint32_t addr) {
    asm volatile("ldmatrix.sync.aligned.m8n8.x4.shared.b16 {%0,%1,%2,%3}, [%4];"
        : "=r"(r[0]), "=r"(r[1]), "=r"(r[2]), "=r"(r[3]) : "r"(addr));
}
__device__ __forceinline__ void mma16816(float* c, const uint32_t* a, const uint32_t* b) {
    asm volatile("mma.sync.aligned.m16n8k16.row.col.f32.f16.f16.f32 "
        "{%0,%1,%2,%3}, {%4,%5,%6,%7}, {%8,%9}, {%0,%1,%2,%3};"
        : "+f"(c[0]), "+f"(c[1]), "+f"(c[2]), "+f"(c[3])
        : "r"(a[0]), "r"(a[1]), "r"(a[2]), "r"(a[3]), "r"(b[0]), "r"(b[1]));
}
#define CP16(dst, src) \
    asm volatile("cp.async.cg.shared.global [%0], [%1], 16;" :: "r"(dst), "l"(src))
#define CP_COMMIT() asm volatile("cp.async.commit_group;" ::: "memory")
#define CP_WAIT0()  asm volatile("cp.async.wait_group 0;" ::: "memory")
#define SWZ(off) ((off) ^ (((off) >> 3) & 0x70))

// ========================= scratch =========================
__device__ __align__(16) __half g_sh[BSZ * NN * NN];
__device__ __align__(16) __half g_xth[3][BSZ * CC * NN];
__device__ __align__(16) __half g_xrh[4][XSZ];
__device__ __align__(16) __half g_xrl[4][XSZ];
__device__ __align__(16) __half g_wt[4 * 128 * 256];
__device__ float g_gcop[4][BSZ * NN * DD];
__device__ float g_cos[PREK * NN * HIDD];
__device__ float g_sin[PREK * NN * HIDD];
__device__ float g_sap[BSZ * PREK * NSPLIT];
__device__ float g_wa[BSZ * PREK];
__device__ float g_att[BSZ * NN * DD];

// ---------------- S -> fp16 (half of batches) ----------------------------
__global__ __launch_bounds__(256) void k_sconv(const float* __restrict__ S, int half)
{
    const int per_half = BSZ * NN * NN / 8;           // float4 count per half
    int i = blockIdx.x * 256 + threadIdx.x;
    if (i >= per_half) return;
    i += half * per_half;
    float4 v = ((const float4*)S)[i];
    __half2* ph = (__half2*)g_sh;
    ph[i * 2]     = __half2(__float2half(v.x), __float2half(v.y));
    ph[i * 2 + 1] = __half2(__float2half(v.z), __float2half(v.w));
}

// ---------------- build x0 ------------------------------------------------
__global__ __launch_bounds__(256) void k_build_x0(const float* __restrict__ inputs,
                                                  const float* __restrict__ hidden)
{
    __shared__ float tile[32][33];
    const int n0 = blockIdx.x * 32;
    const int c0 = blockIdx.y * 32;
    const int b  = blockIdx.z;
    const int lane = threadIdx.x & 31;
    const int wrp  = threadIdx.x >> 5;

#pragma unroll
    for (int r = 0; r < 4; r++) {
        int nl = wrp * 4 + r;
        int n = n0 + nl;
        int c = c0 + lane;
        float v;
        if (c < 64)        v = inputs[((size_t)(b * NN + n)) * 128 + c];
        else if (c < 128)  v = hidden[(((size_t)(b * 4 + 3) * NN + n)) * 128 + (c - 64)];
        else if (c < 192)  v = inputs[((size_t)(b * NN + n)) * 128 + (c - 128 + 64)];
        else               v = hidden[(((size_t)(b * 4 + 3) * NN + n)) * 128 + (c - 192 + 64)];
        __half h = __float2half(v);
        __half l = __float2half(v - __half2float(h));
        size_t o = ((size_t)(b * NN + n)) * CC + c;
        g_xrh[0][o] = h;
        g_xrl[0][o] = l;
        tile[nl][lane] = v;
    }
    __syncthreads();
#pragma unroll
    for (int r = 0; r < 4; r++) {
        int cl = wrp * 4 + r;
        float v = tile[lane][cl];
        size_t o = ((size_t)b * CC + c0 + cl) * NN + n0 + lane;
        g_xth[0][o] = __float2half(v);
    }
}

// ---------------- gc_w -> wt fp16 [m][d][c] ------------------------------
__global__ __launch_bounds__(256) void k_wt(const float* __restrict__ gc_w)
{
    int i = blockIdx.x * 256 + threadIdx.x;
    if (i >= 4 * 128 * 256) return;
    int c = i & 255;
    int d = (i >> 8) & 127;
    int m = i >> 15;
    g_wt[i] = __float2half(gc_w[(size_t)d * 1024 + c * 4 + m]);
}

// ---------------- cos/sin tables ----------------------------------------
__global__ __launch_bounds__(256) void k_cs(const float* __restrict__ R)
{
    int i = blockIdx.x * 256 + threadIdx.x;
    if (i >= PREK * NN * HIDD) return;
    float ph = R[i] * PHASE_SCALE;
    float s, c;
    sincosf(ph, &s, &c);
    g_cos[i] = c;
    g_sin[i] = s;
}

// =================== fp16 1-MMA Chebyshev GEMM (half-batch) ==============
#define CB_STAGE 49152
#define CB_SMEM  (2 * CB_STAGE)

__device__ __forceinline__ void cheb_load512(uint32_t sb, int buf, int tid,
    const __half* A, const __half* B, int k0)
{
    const uint32_t st = sb + buf * CB_STAGE;
#pragma unroll
    for (int i = 0; i < 2; i++) {
        int idx = tid + i * 512;
        int row = idx >> 3;
        int c16 = idx & 7;
        uint32_t off = SWZ((uint32_t)(row * 128 + c16 * 16));
        CP16(st + off, A + (size_t)row * 1024 + k0 + c16 * 8);
    }
#pragma unroll
    for (int i = 0; i < 4; i++) {
        int idx = tid + i * 512;
        int row = idx >> 3;
        int c16 = idx & 7;
        uint32_t off = SWZ((uint32_t)(row * 128 + c16 * 16));
        CP16(st + 16384 + off, B + (size_t)row * 1024 + k0 + c16 * 8);
    }
    CP_COMMIT();
}

__device__ __forceinline__ void hmma_stage512(uint32_t st, int warpM, int warpN,
                                              int lane, float acc[2][8][4])
{
    const int arow = lane & 15;
    const int acol = (lane >> 4) << 4;
    const int g    = lane >> 3;
    const int brow = ((g >> 1) << 3) + (lane & 7);
    const int bcol = (g & 1) << 4;
#pragma unroll
    for (int ks = 0; ks < 4; ks++) {
        uint32_t a[2][4];
#pragma unroll
        for (int mt = 0; mt < 2; mt++) {
            uint32_t off = SWZ((uint32_t)((warpM + mt * 16 + arow) * 128 + ks * 32 + acol));
            ldmx4(a[mt], st + off);
        }
#pragma unroll
        for (int np = 0; np < 4; np++) {
            uint32_t bf[4];
            uint32_t off = SWZ((uint32_t)((warpN + np * 16 + brow) * 128 + ks * 32 + bcol));
            ldmx4(bf, st + 16384 + off);
#pragma unroll
            for (int mt = 0; mt < 2; mt++) {
                mma16816(acc[mt][np * 2],     a[mt], &bf[0]);
                mma16816(acc[mt][np * 2 + 1], a[mt], &bf[2]);
            }
        }
    }
}

__global__ __launch_bounds__(512, 1) void k_cheb_mma(int hop, int b0)
{
    extern __shared__ char smem[];
    const uint32_t sb = smem_to_u32(smem);
    const int tid = threadIdx.x;
    const int wid = tid >> 5;
    const int lane = tid & 31;
    const int row0 = blockIdx.x * 128;
    const int b = blockIdx.y + b0;
    const int warpM = (wid & 3) * 32;
    const int warpN = (wid >> 2) * 64;

    const __half* A = g_sh + ((size_t)b * NN + row0) * NN;
    const __half* B = g_xth[hop] + (size_t)b * CC * NN;

    float acc[2][8][4];
#pragma unroll
    for (int i = 0; i < 2; i++)
#pragma unroll
        for (int j = 0; j < 8; j++)
#pragma unroll
            for (int q = 0; q < 4; q++) acc[i][j][q] = 0.f;

    cheb_load512(sb, 0, tid, A, B, 0);

    for (int s = 0; s < 16; s++) {
        CP_WAIT0();
        __syncthreads();
        if (s + 1 < 16)
            cheb_load512(sb, (s + 1) & 1, tid, A, B, (s + 1) * 64);
        hmma_stage512(sb + (s & 1) * CB_STAGE, warpM, warpN, lane, acc);
    }
    __syncthreads();

    // ---------------- epilogue ----------------
    const int qr = lane >> 2;
    const int qc = (lane & 3) * 2;
    const size_t rmBase = (size_t)b * NN * CC;
    const __half* pH = (hop >= 1) ? g_xrh[hop - 1] : nullptr;
    const __half* pL = (hop >= 1) ? g_xrl[hop - 1] : nullptr;
    __half* oH = g_xrh[hop + 1];
    __half* oL = g_xrl[hop + 1];

    unsigned short* T = (unsigned short*)smem;   // [256][130]

#pragma unroll
    for (int mt = 0; mt < 2; mt++)
#pragma unroll
        for (int half_ = 0; half_ < 2; half_++) {
            int rloc = warpM + mt * 16 + half_ * 8 + qr;
            int row = row0 + rloc;
#pragma unroll
            for (int nt = 0; nt < 8; nt++) {
                int col = warpN + nt * 8 + qc;
                float v0 = acc[mt][nt][half_ * 2 + 0];
                float v1 = acc[mt][nt][half_ * 2 + 1];
                size_t idx = rmBase + (size_t)row * CC + col;
                if (hop >= 1) {
                    __half2 phv = *(const __half2*)(pH + idx);
                    __half2 plv = *(const __half2*)(pL + idx);
                    v0 = 2.f * v0 - (__half2float(phv.x) + __half2float(plv.x));
                    v1 = 2.f * v1 - (__half2float(phv.y) + __half2float(plv.y));
                }
                __half h0 = __float2half(v0);
                __half l0 = __float2half(v0 - __half2float(h0));
                __half h1 = __float2half(v1);
                __half l1 = __float2half(v1 - __half2float(h1));
                *(__half2*)(oH + idx) = __half2(h0, h1);
                *(__half2*)(oL + idx) = __half2(l0, l1);
                if (hop < 2) {
                    T[(uint32_t)col * 130 + rloc]       = __half_as_ushort(h0);
                    T[(uint32_t)(col + 1) * 130 + rloc] = __half_as_ushort(h1);
                }
            }
        }

    if (hop < 2) {
        __syncthreads();
        __half* tH = g_xth[hop + 1] + (size_t)b * CC * NN;
#pragma unroll
        for (int i = 0; i < 32; i++) {
            int idx = tid + i * 512;
            int c = idx >> 6;
            int j = idx & 63;
            uint32_t w = *(const uint32_t*)&T[(uint32_t)c * 130 + 2 * j];
            *(uint32_t*)(tH + (size_t)c * NN + row0 + 2 * j) = w;
        }
    }
}

// =================== fp16 1-MMA gemm2 per-hop partial (K=256) =============
// rbase = starting row (row = b*NN + n space); grid.x covers rows/128.
#define G2_STAGE 32768
#define G2_SMEM  (2 * G2_STAGE)

__global__ __launch_bounds__(256, 2) void k_gemm2_mma(int m, int rbase)
{
    extern __shared__ char smem[];
    const uint32_t sb = smem_to_u32(smem);
    const int tid = threadIdx.x;
    const int wid = tid >> 5;
    const int lane = tid & 31;
    const int row0 = rbase + blockIdx.x * 128;
    const int warpM = (wid & 3) * 32;
    const int warpN = (wid >> 2) * 64;

    float acc[2][8][4];
#pragma unroll
    for (int i = 0; i < 2; i++)
#pragma unroll
        for (int j = 0; j < 8; j++)
#pragma unroll
            for (int q = 0; q < 4; q++) acc[i][j][q] = 0.f;

    const __half* A = g_xrh[m] + (size_t)row0 * 256;
    const __half* B = g_wt + m * 32768;

    auto load = [&](int s, int buf) {
        const int c0 = s * 64;
        const uint32_t st = sb + buf * G2_STAGE;
#pragma unroll
        for (int i = 0; i < 4; i++) {
            int idx = tid + i * 256;
            int row = idx >> 3;
            int c16 = idx & 7;
            uint32_t off = SWZ((uint32_t)(row * 128 + c16 * 16));
            size_t src = (size_t)row * 256 + c0 + c16 * 8;
            CP16(st + off,         A + src);
            CP16(st + 16384 + off, B + src);
        }
        CP_COMMIT();
    };

    const int arow = lane & 15;
    const int acol = (lane >> 4) << 4;
    const int g    = lane >> 3;
    const int brow = ((g >> 1) << 3) + (lane & 7);
    const int bcol = (g & 1) << 4;

    load(0, 0);
    for (int s = 0; s < 4; s++) {
        CP_WAIT0();
        __syncthreads();
        if (s + 1 < 4) load(s + 1, (s + 1) & 1);
        const uint32_t st = sb + (s & 1) * G2_STAGE;
#pragma unroll
        for (int ks = 0; ks < 4; ks++) {
            uint32_t a[2][4];
#pragma unroll
            for (int mt = 0; mt < 2; mt++) {
                uint32_t off = SWZ((uint32_t)((warpM + mt * 16 + arow) * 128 + ks * 32 + acol));
                ldmx4(a[mt], st + off);
            }
#pragma unroll
            for (int np = 0; np < 4; np++) {
                uint32_t bf[4];
                uint32_t off = SWZ((uint32_t)((warpN + np * 16 + brow) * 128 + ks * 32 + bcol));
                ldmx4(bf, st + 16384 + off);
#pragma unroll
                for (int mt = 0; mt < 2; mt++) {
                    mma16816(acc[mt][np * 2],     a[mt], &bf[0]);
                    mma16816(acc[mt][np * 2 + 1], a[mt], &bf[2]);
                }
            }
        }
    }

    float* outp = g_gcop[m];
    const int qr = lane >> 2;
    const int qc = (lane & 3) * 2;
#pragma unroll
    for (int mt = 0; mt < 2; mt++)
#pragma unroll
        for (int half_ = 0; half_ < 2; half_++) {
            int row = row0 + warpM + mt * 16 + half_ * 8 + qr;
#pragma unroll
            for (int nt = 0; nt < 8; nt++) {
                int col = warpN + nt * 8 + qc;
                *(float2*)(outp + (size_t)row * 128 + col) =
                    make_float2(acc[mt][nt][half_ * 2 + 0], acc[mt][nt][half_ * 2 + 1]);
            }
        }
}

// ---------------- sa partials + new_hidden[:,0:3] copy --------------------
__global__ __launch_bounds__(256) void k_sa(const float* __restrict__ hidden,
                                            const float* __restrict__ att_w,
                                            float* __restrict__ out)
{
    const int k  = blockIdx.x;
    const int b  = blockIdx.y;
    const int sp = blockIdx.z;
    const float* hb = hidden + ((size_t)(b * 4 + k) << 17);
    float* cpy = (k >= 1)
        ? (out + OUT0 + (((size_t)(b * 4 + (k - 1))) << 17))
        : nullptr;
    const int tid = threadIdx.x;
    const int base = sp * (NN / NSPLIT) * HIDD;

    float sum = 0.f;
#pragma unroll 4
    for (int ii = tid; ii < (NN / NSPLIT) * HIDD; ii += 256) {
        int i = base + ii;
        int n = i >> 6, h = i & 63;
        float re = hb[(n << 7) + h];
        float im = hb[(n << 7) + 64 + h];
        float c = g_cos[(k << 16) + i];
        float s = g_sin[(k << 16) + i];
        sum += (c * re - s * im) * att_w[(n << 7) + h]
             + (s * re + c * im) * att_w[(n << 7) + 64 + h];
        if (cpy) {
            cpy[(n << 7) + h]      = re;
            cpy[(n << 7) + 64 + h] = im;
        }
    }
    __shared__ float red[8];
    for (int o = 16; o; o >>= 1) sum += __shfl_down_sync(0xffffffffu, sum, o);
    if ((tid & 31) == 0) red[tid >> 5] = sum;
    __syncthreads();
    if (tid < 8) {
        float v = red[tid];
        for (int o = 4; o; o >>= 1) v += __shfl_down_sync(0xffu, v, o);
        if (tid == 0) g_sap[(b * 4 + k) * NSPLIT + sp] = v;
    }
}

// ---------------- combine partials + softmax over k=4 ---------------------
__global__ void k_softmax(const float* __restrict__ att_b)
{
    int b = threadIdx.x;
    if (b >= BSZ) return;
    float s[4];
#pragma unroll
    for (int k = 0; k < 4; k++) {
        float acc = 0.f;
#pragma unroll
        for (int sp = 0; sp < NSPLIT; sp++)
            acc += g_sap[(b * 4 + k) * NSPLIT + sp];
        s[k] = acc + att_b[0];
    }
    float m = fmaxf(fmaxf(s[0], s[1]), fmaxf(s[2], s[3]));
    float e0 = expf(s[0] - m), e1 = expf(s[1] - m);
    float e2 = expf(s[2] - m), e3 = expf(s[3] - m);
    float inv = 1.f / (e0 + e1 + e2 + e3);
    g_wa[b * 4 + 0] = e0 * inv;
    g_wa[b * 4 + 1] = e1 * inv;
    g_wa[b * 4 + 2] = e2 * inv;
    g_wa[b * 4 + 3] = e3 * inv;
}

// ---------------- att[b,n,d] -----------------------------------------------
__global__ __launch_bounds__(256) void k_att(const float* __restrict__ hidden)
{
    int idx = blockIdx.x * 256 + threadIdx.x;
    if (idx >= BSZ * NN * DD) return;
    int d = idx & 127;
    int n = (idx >> 7) & 1023;
    int b = idx >> 17;
    int h = d & 63;
    bool isIm = d >= 64;
    float acc = 0.f;
#pragma unroll
    for (int k = 0; k < 4; k++) {
        const float* hb = hidden + ((size_t)(b * 4 + k) << 17);
        float re = hb[(n << 7) + h];
        float im = hb[(n << 7) + 64 + h];
        float c = g_cos[(k << 16) + (n << 6) + h];
        float s = g_sin[(k << 16) + (n << 6) + h];
        float v = isIm ? (s * re + c * im) : (c * re - s * im);
        acc += g_wa[b * 4 + k] * v;
    }
    g_att[idx] = acc;
}

// ---------------- final (half-batch): combine partials; out = gco@W+b+att --
__global__ __launch_bounds__(256) void k_final(const float* __restrict__ W,
                                               const float* __restrict__ bias,
                                               const float* __restrict__ gc_b,
                                               float* __restrict__ out, int rbase)
{
    const int row0 = rbase + blockIdx.x * 64;
    __shared__ float As[16][68];
    __shared__ float Bs[16][132];
    const int tid = threadIdx.x;
    const int a_r = tid >> 2;
    const int a_c = (tid & 3) << 2;
    const int b_r = tid >> 5;
    const int b_c = (tid & 31) << 2;
    const int ty  = tid >> 4;
    const int tx  = tid & 15;

    float acc[4][8];
#pragma unroll
    for (int i = 0; i < 4; i++)
#pragma unroll
        for (int j = 0; j < 8; j++) acc[i][j] = 0.f;

    for (int k0 = 0; k0 < 128; k0 += 16) {
        size_t aoff = (size_t)(row0 + a_r) * 128 + k0 + a_c;
        float4 p0 = *(const float4*)(&g_gcop[0][0] + aoff);
        float4 p1 = *(const float4*)(&g_gcop[1][0] + aoff);
        float4 p2 = *(const float4*)(&g_gcop[2][0] + aoff);
        float4 p3 = *(const float4*)(&g_gcop[3][0] + aoff);
        float4 gb = *(const float4*)(gc_b + k0 + a_c);
        float4 av;
        av.x = p0.x + p1.x + p2.x + p3.x + gb.x; av.x = (av.x >= 0.f) ? av.x : 0.01f * av.x;
        av.y = p0.y + p1.y + p2.y + p3.y + gb.y; av.y = (av.y >= 0.f) ? av.y : 0.01f * av.y;
        av.z = p0.z + p1.z + p2.z + p3.z + gb.z; av.z = (av.z >= 0.f) ? av.z : 0.01f * av.z;
        av.w = p0.w + p1.w + p2.w + p3.w + gb.w; av.w = (av.w >= 0.f) ? av.w : 0.01f * av.w;
        float4 b0 = *(const float4*)(W + (size_t)(k0 + b_r) * 128 + b_c);
        float4 b1 = *(const float4*)(W + (size_t)(k0 + b_r + 8) * 128 + b_c);
        __syncthreads();
        As[a_c + 0][a_r] = av.x; As[a_c + 1][a_r] = av.y;
        As[a_c + 2][a_r] = av.z; As[a_c + 3][a_r] = av.w;
        *(float4*)&Bs[b_r][b_c]     = b0;
        *(float4*)&Bs[b_r + 8][b_c] = b1;
        __syncthreads();
#pragma unroll
        for (int kk = 0; kk < 16; kk++) {
            float ar[4], br[8];
            *(float4*)&ar[0] = *(const float4*)&As[kk][ty * 4];
            *(float4*)&br[0] = *(const float4*)&Bs[kk][tx * 8];
            *(float4*)&br[4] = *(const float4*)&Bs[kk][tx * 8 + 4];
#pragma unroll
            for (int i = 0; i < 4; i++)
#pragma unroll
                for (int j = 0; j < 8; j++) acc[i][j] += ar[i] * br[j];
        }
    }

#pragma unroll
    for (int i = 0; i < 4; i++) {
        int rr = row0 + ty * 4 + i;
        int b  = rr >> 10;
        int n  = rr & 1023;
        size_t nh_off = (size_t)OUT0 + (((size_t)(b * 4 + 3) << 10 | n) << 7);
#pragma unroll
        for (int j = 0; j < 8; j += 4) {
            int col = tx * 8 + j;
            float4 at = *(const float4*)(g_att + (size_t)rr * 128 + col);
            float4 bi = *(const float4*)(bias + (size_t)n * 128 + col);
            float4 v;
            v.x = acc[i][j + 0] + bi.x + at.x;
            v.y = acc[i][j + 1] + bi.y + at.y;
            v.z = acc[i][j + 2] + bi.z + at.z;
            v.w = acc[i][j + 3] + bi.w + at.w;
            *(float4*)(out + (size_t)rr * 128 + col) = v;
            *(float4*)(out + nh_off + col)           = v;
        }
    }
}

// ---------------- launch (batch-split pipelined DAG) -------------------------
extern "C" void kernel_launch(void* const* d_in, const int* in_sizes, int n_in,
                              void* d_out, int out_size)
{
    const float* inputs   = (const float*)d_in[0];
    const float* supports = (const float*)d_in[1];
    const float* hidden   = (const float*)d_in[2];
    const float* W        = (const float*)d_in[3];
    const float* bias     = (const float*)d_in[4];
    const float* R        = (const float*)d_in[5];
    const float* gc_w  = (const float*)d_in[6];
    const float* gc_b  = (const float*)d_in[7];
    const float* att_w = (const float*)d_in[10];
    const float* att_b = (const float*)d_in[11];
    float* out = (float*)d_out;

    static cudaStream_t sB = nullptr, sSide = nullptr, sAtt = nullptr;
    static cudaEvent_t evF, evA, evD, evC, ev0A, ev0B, ev1A, ev1B, evP;
    static bool init = false;
    if (!init) {
        cudaStreamCreateWithFlags(&sB, cudaStreamNonBlocking);
        cudaStreamCreateWithFlags(&sSide, cudaStreamNonBlocking);
        cudaStreamCreateWithFlags(&sAtt, cudaStreamNonBlocking);
        cudaEventCreateWithFlags(&evF, cudaEventDisableTiming);
        cudaEventCreateWithFlags(&evA, cudaEventDisableTiming);
        cudaEventCreateWithFlags(&evD, cudaEventDisableTiming);
        cudaEventCreateWithFlags(&evC, cudaEventDisableTiming);
        cudaEventCreateWithFlags(&ev0A, cudaEventDisableTiming);
        cudaEventCreateWithFlags(&ev0B, cudaEventDisableTiming);
        cudaEventCreateWithFlags(&ev1A, cudaEventDisableTiming);
        cudaEventCreateWithFlags(&ev1B, cudaEventDisableTiming);
        cudaEventCreateWithFlags(&evP, cudaEventDisableTiming);
        cudaFuncSetAttribute(k_cheb_mma, cudaFuncAttributeMaxDynamicSharedMemorySize, CB_SMEM);
        cudaFuncSetAttribute(k_gemm2_mma, cudaFuncAttributeMaxDynamicSharedMemorySize, G2_SMEM);
        init = true;
    }

    cudaStream_t sA = 0;
    const int scBlocks = (BSZ * NN * NN / 8 + 255) / 256;
    const dim3 gHalf(8, 8);              // 8 m-tiles x 8 batches

    // fork
    cudaEventRecord(evF, sA);
    cudaStreamWaitEvent(sB, evF, 0);
    cudaStreamWaitEvent(sSide, evF, 0);

    // half A / half B sconv (parallel)
    k_sconv<<<scBlocks, 256, 0, sA>>>(supports, 0);
    k_sconv<<<scBlocks, 256, 0, sB>>>(supports, 1);

    // side chain
    k_build_x0<<<dim3(NN / 32, CC / 32, BSZ), 256, 0, sSide>>>(inputs, hidden);
    cudaEventRecord(evA, sSide);                     // x0 ready
    k_cs<<<(PREK * NN * HIDD + 255) / 256, 256, 0, sSide>>>(R);
    cudaEventRecord(evD, sSide);                     // cs done
    k_wt<<<(4 * 128 * 256 + 255) / 256, 256, 0, sSide>>>(gc_w);

    // att chain
    cudaStreamWaitEvent(sAtt, evD, 0);
    k_sa<<<dim3(PREK, BSZ, NSPLIT), 256, 0, sAtt>>>(hidden, att_w, out);
    k_softmax<<<1, 32, 0, sAtt>>>(att_b);
    k_att<<<(BSZ * NN * DD + 255) / 256, 256, 0, sAtt>>>(hidden);
    cudaEventRecord(evC, sAtt);                      // att done

    // ladder A (batches 0-7) on sA
    cudaStreamWaitEvent(sA, evA, 0);
    k_cheb_mma<<<gHalf, 512, CB_SMEM, sA>>>(0, 0);
    cudaEventRecord(ev0A, sA);
    k_cheb_mma<<<gHalf, 512, CB_SMEM, sA>>>(1, 0);
    cudaEventRecord(ev1A, sA);
    k_cheb_mma<<<gHalf, 512, CB_SMEM, sA>>>(2, 0);

    // ladder B (batches 8-15) on sB
    cudaStreamWaitEvent(sB, evA, 0);
    k_cheb_mma<<<gHalf, 512, CB_SMEM, sB>>>(0, 8);
    cudaEventRecord(ev0B, sB);
    k_cheb_mma<<<gHalf, 512, CB_SMEM, sB>>>(1, 8);
    cudaEventRecord(ev1B, sB);
    k_cheb_mma<<<gHalf, 512, CB_SMEM, sB>>>(2, 8);

    // gemm2 partials m0-m2 (whole) on sSide, gated on both halves
    k_gemm2_mma<<<128, 256, G2_SMEM, sSide>>>(0, 0);       // after wt; x0 via build_x0 order
    cudaStreamWaitEvent(sSide, ev0A, 0);
    cudaStreamWaitEvent(sSide, ev0B, 0);
    k_gemm2_mma<<<128, 256, G2_SMEM, sSide>>>(1, 0);
    cudaStreamWaitEvent(sSide, ev1A, 0);
    cudaStreamWaitEvent(sSide, ev1B, 0);
    k_gemm2_mma<<<128, 256, G2_SMEM, sSide>>>(2, 0);
    cudaEventRecord(evP, sSide);                     // m0-2 done

    // m3 + final per half (m3 needs that half's cheb2; program order on stream)
    k_gemm2_mma<<<64, 256, G2_SMEM, sA>>>(3, 0);
    cudaStreamWaitEvent(sA, evP, 0);
    cudaStreamWaitEvent(sA, evC, 0);
    k_final<<<128, 256, 0, sA>>>(W, bias, gc_b, out, 0);

    k_gemm2_mma<<<64, 256, G2_SMEM, sB>>>(3, 8 * NN);
    cudaStreamWaitEvent(sB, evP, 0);
    cudaStreamWaitEvent(sB, evC, 0);
    k_final<<<128, 256, 0, sB>>>(W, bias, gc_b, out, 8 * NN);

    // join: sA must not return before sB's final (graph end node ordering)
    cudaEventRecord(evF, sB);
    cudaStreamWaitEvent(sA, evF, 0);
}

// round 17
// speedup vs baseline: 1.0669x; 1.0669x over previous
#include <cuda_runtime.h>
#include <cuda_fp16.h>
#include <cstdint>

#define BSZ   16
#define NN    1024
#define HIDD  64
#define DD    128
#define CC    256
#define PREK  4
#define NSPLIT 16

#define XSZ   (BSZ * NN * CC)
#define OUT0  (BSZ * NN * DD)

#define PHASE_SCALE ((float)(3.141592653589793 / 0.21875))

// ===================== base-ISA tensor helpers (sm_80+) =====================
__device__ __forceinline__ uint32_t smem_to_u32(const void* p) {
    uint32_t a;
    asm("{ .reg .u64 t; cvta.to.shared.u64 t, %1; cvt.u32.u64 %0, t; }" : "=r"(a) : "l"(p));
    return a;
}
__device__ __forceinline__ void ldmx4(uint32_t* r, uint32_t addr) {
    asm volatile("ldmatrix.sync.aligned.m8n8.x4.shared.b16 {%0,%1,%2,%3}, [%4];"
        : "=r"(r[0]), "=r"(r[1]), "=r"(r[2]), "=r"(r[3]) : "r"(addr));
}
__device__ __forceinline__ void mma16816(float* c, const uint32_t* a, const uint32_t* b) {
    asm volatile("mma.sync.aligned.m16n8k16.row.col.f32.f16.f16.f32 "
        "{%0,%1,%2,%3}, {%4,%5,%6,%7}, {%8,%9}, {%0,%1,%2,%3};"
        : "+f"(c[0]), "+f"(c[1]), "+f"(c[2]), "+f"(c[3])
        : "r"(a[0]), "r"(a[1]), "r"(a[2]), "r"(a[3]), "r"(b[0]), "r"(b[1]));
}
#define CP16(dst, src) \
    asm volatile("cp.async.cg.shared.global [%0], [%1], 16;" :: "r"(dst), "l"(src))
#define CP_COMMIT() asm volatile("cp.async.commit_group;" ::: "memory")
#define CP_WAIT0()  asm volatile("cp.async.wait_group 0;" ::: "memory")
#define SWZ(off) ((off) ^ (((off) >> 3) & 0x70))

// ========================= scratch =========================
__device__ __align__(16) __half g_sh[BSZ * NN * NN];
__device__ __align__(16) __half g_xth[3][BSZ * CC * NN];
__device__ __align__(16) __half g_xrh[4][XSZ];
__device__ __align__(16) __half g_xrl[4][XSZ];
__device__ __align__(16) __half g_wt[4 * 128 * 256];
__device__ float g_gcop[4][BSZ * NN * DD];
__device__ float g_cos[PREK * NN * HIDD];
__device__ float g_sin[PREK * NN * HIDD];
__device__ float g_sap[BSZ * PREK * NSPLIT];
__device__ float g_wa[BSZ * PREK];
__device__ float g_att[BSZ * NN * DD];

// ---------------- S -> fp16 ---------------------------------------------
__global__ __launch_bounds__(256) void k_sconv(const float* __restrict__ S)
{
    int i = blockIdx.x * 256 + threadIdx.x;
    const int total = BSZ * NN * NN / 4;
    if (i >= total) return;
    float4 v = ((const float4*)S)[i];
    __half2* ph = (__half2*)g_sh;
    ph[i * 2]     = __half2(__float2half(v.x), __float2half(v.y));
    ph[i * 2 + 1] = __half2(__float2half(v.z), __float2half(v.w));
}

// ---------------- build x0 ------------------------------------------------
__global__ __launch_bounds__(256) void k_build_x0(const float* __restrict__ inputs,
                                                  const float* __restrict__ hidden)
{
    __shared__ float tile[32][33];
    const int n0 = blockIdx.x * 32;
    const int c0 = blockIdx.y * 32;
    const int b  = blockIdx.z;
    const int lane = threadIdx.x & 31;
    const int wrp  = threadIdx.x >> 5;

#pragma unroll
    for (int r = 0; r < 4; r++) {
        int nl = wrp * 4 + r;
        int n = n0 + nl;
        int c = c0 + lane;
        float v;
        if (c < 64)        v = inputs[((size_t)(b * NN + n)) * 128 + c];
        else if (c < 128)  v = hidden[(((size_t)(b * 4 + 3) * NN + n)) * 128 + (c - 64)];
        else if (c < 192)  v = inputs[((size_t)(b * NN + n)) * 128 + (c - 128 + 64)];
        else               v = hidden[(((size_t)(b * 4 + 3) * NN + n)) * 128 + (c - 192 + 64)];
        __half h = __float2half(v);
        __half l = __float2half(v - __half2float(h));
        size_t o = ((size_t)(b * NN + n)) * CC + c;
        g_xrh[0][o] = h;
        g_xrl[0][o] = l;
        tile[nl][lane] = v;
    }
    __syncthreads();
#pragma unroll
    for (int r = 0; r < 4; r++) {
        int cl = wrp * 4 + r;
        float v = tile[lane][cl];
        size_t o = ((size_t)b * CC + c0 + cl) * NN + n0 + lane;
        g_xth[0][o] = __float2half(v);
    }
}

// ---------------- gc_w -> wt fp16 [m][d][c] ------------------------------
__global__ __launch_bounds__(256) void k_wt(const float* __restrict__ gc_w)
{
    int i = blockIdx.x * 256 + threadIdx.x;
    if (i >= 4 * 128 * 256) return;
    int c = i & 255;
    int d = (i >> 8) & 127;
    int m = i >> 15;
    g_wt[i] = __float2half(gc_w[(size_t)d * 1024 + c * 4 + m]);
}

// ---------------- cos/sin tables ----------------------------------------
__global__ __launch_bounds__(256) void k_cs(const float* __restrict__ R)
{
    int i = blockIdx.x * 256 + threadIdx.x;
    if (i >= PREK * NN * HIDD) return;
    float ph = R[i] * PHASE_SCALE;
    float s, c;
    sincosf(ph, &s, &c);
    g_cos[i] = c;
    g_sin[i] = s;
}

// =================== fp16 1-MMA Chebyshev GEMM ===========================
#define CB_STAGE 49152
#define CB_SMEM  (2 * CB_STAGE)

__device__ __forceinline__ void cheb_load512(uint32_t sb, int buf, int tid,
    const __half* A, const __half* B, int k0)
{
    const uint32_t st = sb + buf * CB_STAGE;
#pragma unroll
    for (int i = 0; i < 2; i++) {
        int idx = tid + i * 512;
        int row = idx >> 3;
        int c16 = idx & 7;
        uint32_t off = SWZ((uint32_t)(row * 128 + c16 * 16));
        CP16(st + off, A + (size_t)row * 1024 + k0 + c16 * 8);
    }
#pragma unroll
    for (int i = 0; i < 4; i++) {
        int idx = tid + i * 512;
        int row = idx >> 3;
        int c16 = idx & 7;
        uint32_t off = SWZ((uint32_t)(row * 128 + c16 * 16));
        CP16(st + 16384 + off, B + (size_t)row * 1024 + k0 + c16 * 8);
    }
    CP_COMMIT();
}

__device__ __forceinline__ void hmma_stage512(uint32_t st, int warpM, int warpN,
                                              int lane, float acc[2][8][4])
{
    const int arow = lane & 15;
    const int acol = (lane >> 4) << 4;
    const int g    = lane >> 3;
    const int brow = ((g >> 1) << 3) + (lane & 7);
    const int bcol = (g & 1) << 4;
#pragma unroll
    for (int ks = 0; ks < 4; ks++) {
        uint32_t a[2][4];
#pragma unroll
        for (int mt = 0; mt < 2; mt++) {
            uint32_t off = SWZ((uint32_t)((warpM + mt * 16 + arow) * 128 + ks * 32 + acol));
            ldmx4(a[mt], st + off);
        }
#pragma unroll
        for (int np = 0; np < 4; np++) {
            uint32_t bf[4];
            uint32_t off = SWZ((uint32_t)((warpN + np * 16 + brow) * 128 + ks * 32 + bcol));
            ldmx4(bf, st + 16384 + off);
#pragma unroll
            for (int mt = 0; mt < 2; mt++) {
                mma16816(acc[mt][np * 2],     a[mt], &bf[0]);
                mma16816(acc[mt][np * 2 + 1], a[mt], &bf[2]);
            }
        }
    }
}

__global__ __launch_bounds__(512, 1) void k_cheb_mma(int hop)
{
    extern __shared__ char smem[];
    const uint32_t sb = smem_to_u32(smem);
    const int tid = threadIdx.x;
    const int wid = tid >> 5;
    const int lane = tid & 31;
    const int row0 = blockIdx.x * 128;
    const int b = blockIdx.y;
    const int warpM = (wid & 3) * 32;
    const int warpN = (wid >> 2) * 64;

    const __half* A = g_sh + ((size_t)b * NN + row0) * NN;
    const __half* B = g_xth[hop] + (size_t)b * CC * NN;

    float acc[2][8][4];
#pragma unroll
    for (int i = 0; i < 2; i++)
#pragma unroll
        for (int j = 0; j < 8; j++)
#pragma unroll
            for (int q = 0; q < 4; q++) acc[i][j][q] = 0.f;

    cheb_load512(sb, 0, tid, A, B, 0);

    for (int s = 0; s < 16; s++) {
        CP_WAIT0();
        __syncthreads();
        if (s + 1 < 16)
            cheb_load512(sb, (s + 1) & 1, tid, A, B, (s + 1) * 64);
        hmma_stage512(sb + (s & 1) * CB_STAGE, warpM, warpN, lane, acc);
    }
    __syncthreads();

    // ---------------- epilogue ----------------
    const int qr = lane >> 2;
    const int qc = (lane & 3) * 2;
    const size_t rmBase = (size_t)b * NN * CC;
    const __half* pH = (hop >= 1) ? g_xrh[hop - 1] : nullptr;
    const __half* pL = (hop >= 1) ? g_xrl[hop - 1] : nullptr;
    __half* oH = g_xrh[hop + 1];
    __half* oL = g_xrl[hop + 1];

    unsigned short* T = (unsigned short*)smem;   // [256][130]

#pragma unroll
    for (int mt = 0; mt < 2; mt++)
#pragma unroll
        for (int half_ = 0; half_ < 2; half_++) {
            int rloc = warpM + mt * 16 + half_ * 8 + qr;
            int row = row0 + rloc;
#pragma unroll
            for (int nt = 0; nt < 8; nt++) {
                int col = warpN + nt * 8 + qc;
                float v0 = acc[mt][nt][half_ * 2 + 0];
                float v1 = acc[mt][nt][half_ * 2 + 1];
                size_t idx = rmBase + (size_t)row * CC + col;
                if (hop >= 1) {
                    __half2 phv = *(const __half2*)(pH + idx);
                    __half2 plv = *(const __half2*)(pL + idx);
                    v0 = 2.f * v0 - (__half2float(phv.x) + __half2float(plv.x));
                    v1 = 2.f * v1 - (__half2float(phv.y) + __half2float(plv.y));
                }
                __half h0 = __float2half(v0);
                __half h1 = __float2half(v1);
                *(__half2*)(oH + idx) = __half2(h0, h1);
                if (hop < 2) {   // lo part only needed while a next hop exists
                    __half l0 = __float2half(v0 - __half2float(h0));
                    __half l1 = __float2half(v1 - __half2float(h1));
                    *(__half2*)(oL + idx) = __half2(l0, l1);
                    T[(uint32_t)col * 130 + rloc]       = __half_as_ushort(h0);
                    T[(uint32_t)(col + 1) * 130 + rloc] = __half_as_ushort(h1);
                }
            }
        }

    if (hop < 2) {
        __syncthreads();
        __half* tH = g_xth[hop + 1] + (size_t)b * CC * NN;
#pragma unroll
        for (int i = 0; i < 32; i++) {
            int idx = tid + i * 512;
            int c = idx >> 6;
            int j = idx & 63;
            uint32_t w = *(const uint32_t*)&T[(uint32_t)c * 130 + 2 * j];
            *(uint32_t*)(tH + (size_t)c * NN + row0 + 2 * j) = w;
        }
    }
}

// =================== fp16 1-MMA gemm2 per-hop partial (K=256) =============
#define G2_STAGE 32768
#define G2_SMEM  (2 * G2_STAGE)

__global__ __launch_bounds__(256, 2) void k_gemm2_mma(int m)
{
    extern __shared__ char smem[];
    const uint32_t sb = smem_to_u32(smem);
    const int tid = threadIdx.x;
    const int wid = tid >> 5;
    const int lane = tid & 31;
    const int row0 = blockIdx.x * 128;
    const int warpM = (wid & 3) * 32;
    const int warpN = (wid >> 2) * 64;

    float acc[2][8][4];
#pragma unroll
    for (int i = 0; i < 2; i++)
#pragma unroll
        for (int j = 0; j < 8; j++)
#pragma unroll
            for (int q = 0; q < 4; q++) acc[i][j][q] = 0.f;

    const __half* A = g_xrh[m] + (size_t)row0 * 256;
    const __half* B = g_wt + m * 32768;

    auto load = [&](int s, int buf) {
        const int c0 = s * 64;
        const uint32_t st = sb + buf * G2_STAGE;
#pragma unroll
        for (int i = 0; i < 4; i++) {
            int idx = tid + i * 256;
            int row = idx >> 3;
            int c16 = idx & 7;
            uint32_t off = SWZ((uint32_t)(row * 128 + c16 * 16));
            size_t src = (size_t)row * 256 + c0 + c16 * 8;
            CP16(st + off,         A + src);
            CP16(st + 16384 + off, B + src);
        }
        CP_COMMIT();
    };

    const int arow = lane & 15;
    const int acol = (lane >> 4) << 4;
    const int g    = lane >> 3;
    const int brow = ((g >> 1) << 3) + (lane & 7);
    const int bcol = (g & 1) << 4;

    load(0, 0);
    for (int s = 0; s < 4; s++) {
        CP_WAIT0();
        __syncthreads();
        if (s + 1 < 4) load(s + 1, (s + 1) & 1);
        const uint32_t st = sb + (s & 1) * G2_STAGE;
#pragma unroll
        for (int ks = 0; ks < 4; ks++) {
            uint32_t a[2][4];
#pragma unroll
            for (int mt = 0; mt < 2; mt++) {
                uint32_t off = SWZ((uint32_t)((warpM + mt * 16 + arow) * 128 + ks * 32 + acol));
                ldmx4(a[mt], st + off);
            }
#pragma unroll
            for (int np = 0; np < 4; np++) {
                uint32_t bf[4];
                uint32_t off = SWZ((uint32_t)((warpN + np * 16 + brow) * 128 + ks * 32 + bcol));
                ldmx4(bf, st + 16384 + off);
#pragma unroll
                for (int mt = 0; mt < 2; mt++) {
                    mma16816(acc[mt][np * 2],     a[mt], &bf[0]);
                    mma16816(acc[mt][np * 2 + 1], a[mt], &bf[2]);
                }
            }
        }
    }

    float* outp = g_gcop[m];
    const int qr = lane >> 2;
    const int qc = (lane & 3) * 2;
#pragma unroll
    for (int mt = 0; mt < 2; mt++)
#pragma unroll
        for (int half_ = 0; half_ < 2; half_++) {
            int row = row0 + warpM + mt * 16 + half_ * 8 + qr;
#pragma unroll
            for (int nt = 0; nt < 8; nt++) {
                int col = warpN + nt * 8 + qc;
                *(float2*)(outp + (size_t)row * 128 + col) =
                    make_float2(acc[mt][nt][half_ * 2 + 0], acc[mt][nt][half_ * 2 + 1]);
            }
        }
}

// ---------------- sa partials + new_hidden[:,0:3] copy --------------------
__global__ __launch_bounds__(256) void k_sa(const float* __restrict__ hidden,
                                            const float* __restrict__ att_w,
                                            float* __restrict__ out)
{
    const int k  = blockIdx.x;
    const int b  = blockIdx.y;
    const int sp = blockIdx.z;
    const float* hb = hidden + ((size_t)(b * 4 + k) << 17);
    float* cpy = (k >= 1)
        ? (out + OUT0 + (((size_t)(b * 4 + (k - 1))) << 17))
        : nullptr;
    const int tid = threadIdx.x;
    const int base = sp * (NN / NSPLIT) * HIDD;

    float sum = 0.f;
#pragma unroll 4
    for (int ii = tid; ii < (NN / NSPLIT) * HIDD; ii += 256) {
        int i = base + ii;
        int n = i >> 6, h = i & 63;
        float re = hb[(n << 7) + h];
        float im = hb[(n << 7) + 64 + h];
        float c = g_cos[(k << 16) + i];
        float s = g_sin[(k << 16) + i];
        sum += (c * re - s * im) * att_w[(n << 7) + h]
             + (s * re + c * im) * att_w[(n << 7) + 64 + h];
        if (cpy) {
            cpy[(n << 7) + h]      = re;
            cpy[(n << 7) + 64 + h] = im;
        }
    }
    __shared__ float red[8];
    for (int o = 16; o; o >>= 1) sum += __shfl_down_sync(0xffffffffu, sum, o);
    if ((tid & 31) == 0) red[tid >> 5] = sum;
    __syncthreads();
    if (tid < 8) {
        float v = red[tid];
        for (int o = 4; o; o >>= 1) v += __shfl_down_sync(0xffu, v, o);
        if (tid == 0) g_sap[(b * 4 + k) * NSPLIT + sp] = v;
    }
}

// ---------------- combine partials + softmax over k=4 ---------------------
__global__ void k_softmax(const float* __restrict__ att_b)
{
    int b = threadIdx.x;
    if (b >= BSZ) return;
    float s[4];
#pragma unroll
    for (int k = 0; k < 4; k++) {
        float acc = 0.f;
#pragma unroll
        for (int sp = 0; sp < NSPLIT; sp++)
            acc += g_sap[(b * 4 + k) * NSPLIT + sp];
        s[k] = acc + att_b[0];
    }
    float m = fmaxf(fmaxf(s[0], s[1]), fmaxf(s[2], s[3]));
    float e0 = expf(s[0] - m), e1 = expf(s[1] - m);
    float e2 = expf(s[2] - m), e3 = expf(s[3] - m);
    float inv = 1.f / (e0 + e1 + e2 + e3);
    g_wa[b * 4 + 0] = e0 * inv;
    g_wa[b * 4 + 1] = e1 * inv;
    g_wa[b * 4 + 2] = e2 * inv;
    g_wa[b * 4 + 3] = e3 * inv;
}

// ---------------- att[b,n,d] (precomputed, overlaps cheb) -----------------
__global__ __launch_bounds__(256) void k_att(const float* __restrict__ hidden)
{
    int idx = blockIdx.x * 256 + threadIdx.x;
    if (idx >= BSZ * NN * DD) return;
    int d = idx & 127;
    int n = (idx >> 7) & 1023;
    int b = idx >> 17;
    int h = d & 63;
    bool isIm = d >= 64;
    float acc = 0.f;
#pragma unroll
    for (int k = 0; k < 4; k++) {
        const float* hb = hidden + ((size_t)(b * 4 + k) << 17);
        float re = hb[(n << 7) + h];
        float im = hb[(n << 7) + 64 + h];
        float c = g_cos[(k << 16) + (n << 6) + h];
        float s = g_sin[(k << 16) + (n << 6) + h];
        float v = isIm ? (s * re + c * im) : (c * re - s * im);
        acc += g_wa[b * 4 + k] * v;
    }
    g_att[idx] = acc;
}

// ---------------- final: combine 4 gemm2 partials; out = gco@W+b+att -------
__global__ __launch_bounds__(256) void k_final(const float* __restrict__ W,
                                               const float* __restrict__ bias,
                                               const float* __restrict__ gc_b,
                                               float* __restrict__ out)
{
    const int row0 = blockIdx.x * 64;
    __shared__ float As[16][68];
    __shared__ float Bs[16][132];
    const int tid = threadIdx.x;
    const int a_r = tid >> 2;
    const int a_c = (tid & 3) << 2;
    const int b_r = tid >> 5;
    const int b_c = (tid & 31) << 2;
    const int ty  = tid >> 4;
    const int tx  = tid & 15;

    float acc[4][8];
#pragma unroll
    for (int i = 0; i < 4; i++)
#pragma unroll
        for (int j = 0; j < 8; j++) acc[i][j] = 0.f;

    for (int k0 = 0; k0 < 128; k0 += 16) {
        size_t aoff = (size_t)(row0 + a_r) * 128 + k0 + a_c;
        float4 p0 = *(const float4*)(&g_gcop[0][0] + aoff);
        float4 p1 = *(const float4*)(&g_gcop[1][0] + aoff);
        float4 p2 = *(const float4*)(&g_gcop[2][0] + aoff);
        float4 p3 = *(const float4*)(&g_gcop[3][0] + aoff);
        float4 gb = *(const float4*)(gc_b + k0 + a_c);
        float4 av;
        av.x = p0.x + p1.x + p2.x + p3.x + gb.x; av.x = (av.x >= 0.f) ? av.x : 0.01f * av.x;
        av.y = p0.y + p1.y + p2.y + p3.y + gb.y; av.y = (av.y >= 0.f) ? av.y : 0.01f * av.y;
        av.z = p0.z + p1.z + p2.z + p3.z + gb.z; av.z = (av.z >= 0.f) ? av.z : 0.01f * av.z;
        av.w = p0.w + p1.w + p2.w + p3.w + gb.w; av.w = (av.w >= 0.f) ? av.w : 0.01f * av.w;
        float4 b0 = *(const float4*)(W + (size_t)(k0 + b_r) * 128 + b_c);
        float4 b1 = *(const float4*)(W + (size_t)(k0 + b_r + 8) * 128 + b_c);
        __syncthreads();
        As[a_c + 0][a_r] = av.x; As[a_c + 1][a_r] = av.y;
        As[a_c + 2][a_r] = av.z; As[a_c + 3][a_r] = av.w;
        *(float4*)&Bs[b_r][b_c]     = b0;
        *(float4*)&Bs[b_r + 8][b_c] = b1;
        __syncthreads();
#pragma unroll
        for (int kk = 0; kk < 16; kk++) {
            float ar[4], br[8];
            *(float4*)&ar[0] = *(const float4*)&As[kk][ty * 4];
            *(float4*)&br[0] = *(const float4*)&Bs[kk][tx * 8];
            *(float4*)&br[4] = *(const float4*)&Bs[kk][tx * 8 + 4];
#pragma unroll
            for (int i = 0; i < 4; i++)
#pragma unroll
                for (int j = 0; j < 8; j++) acc[i][j] += ar[i] * br[j];
        }
    }

#pragma unroll
    for (int i = 0; i < 4; i++) {
        int rr = row0 + ty * 4 + i;
        int b  = rr >> 10;
        int n  = rr & 1023;
        size_t nh_off = (size_t)OUT0 + (((size_t)(b * 4 + 3) << 10 | n) << 7);
#pragma unroll
        for (int j = 0; j < 8; j += 4) {
            int col = tx * 8 + j;
            float4 at = *(const float4*)(g_att + (size_t)rr * 128 + col);
            float4 bi = *(const float4*)(bias + (size_t)n * 128 + col);
            float4 v;
            v.x = acc[i][j + 0] + bi.x + at.x;
            v.y = acc[i][j + 1] + bi.y + at.y;
            v.z = acc[i][j + 2] + bi.z + at.z;
            v.w = acc[i][j + 3] + bi.w + at.w;
            *(float4*)(out + (size_t)rr * 128 + col) = v;
            *(float4*)(out + nh_off + col)           = v;
        }
    }
}

// ---------------- launch (stream-parallel DAG v3, r15 structure) ------------
extern "C" void kernel_launch(void* const* d_in, const int* in_sizes, int n_in,
                              void* d_out, int out_size)
{
    const float* inputs   = (const float*)d_in[0];
    const float* supports = (const float*)d_in[1];
    const float* hidden   = (const float*)d_in[2];
    const float* W        = (const float*)d_in[3];
    const float* bias     = (const float*)d_in[4];
    const float* R        = (const float*)d_in[5];
    const float* gc_w  = (const float*)d_in[6];
    const float* gc_b  = (const float*)d_in[7];
    const float* att_w = (const float*)d_in[10];
    const float* att_b = (const float*)d_in[11];
    float* out = (float*)d_out;

    static cudaStream_t s1 = nullptr, s2 = nullptr;
    static cudaEvent_t evF, evA, evD, evC, ev1, ev2, evG;
    static bool init = false;
    if (!init) {
        cudaStreamCreateWithFlags(&s1, cudaStreamNonBlocking);
        cudaStreamCreateWithFlags(&s2, cudaStreamNonBlocking);
        cudaEventCreateWithFlags(&evF, cudaEventDisableTiming);
        cudaEventCreateWithFlags(&evA, cudaEventDisableTiming);
        cudaEventCreateWithFlags(&evD, cudaEventDisableTiming);
        cudaEventCreateWithFlags(&evC, cudaEventDisableTiming);
        cudaEventCreateWithFlags(&ev1, cudaEventDisableTiming);
        cudaEventCreateWithFlags(&ev2, cudaEventDisableTiming);
        cudaEventCreateWithFlags(&evG, cudaEventDisableTiming);
        cudaFuncSetAttribute(k_cheb_mma, cudaFuncAttributeMaxDynamicSharedMemorySize, CB_SMEM);
        cudaFuncSetAttribute(k_gemm2_mma, cudaFuncAttributeMaxDynamicSharedMemorySize, G2_SMEM);
        init = true;
    }

    cudaStream_t s0 = 0;

    // fork s1 from s0
    cudaEventRecord(evF, s0);
    cudaStreamWaitEvent(s1, evF, 0);

    // s0: long chain head
    k_sconv<<<(BSZ * NN * NN / 4 + 255) / 256, 256, 0, s0>>>(supports);

    // s1: side chain
    k_build_x0<<<dim3(NN / 32, CC / 32, BSZ), 256, 0, s1>>>(inputs, hidden);
    cudaEventRecord(evA, s1);                       // x0 ready
    k_cs<<<(PREK * NN * HIDD + 255) / 256, 256, 0, s1>>>(R);
    cudaEventRecord(evD, s1);                       // cs done
    k_wt<<<(4 * 128 * 256 + 255) / 256, 256, 0, s1>>>(gc_w);

    // s2: sa -> softmax -> att (all inside cheb window)
    cudaStreamWaitEvent(s2, evD, 0);
    k_sa<<<dim3(PREK, BSZ, NSPLIT), 256, 0, s2>>>(hidden, att_w, out);
    k_softmax<<<1, 32, 0, s2>>>(att_b);
    k_att<<<(BSZ * NN * DD + 255) / 256, 256, 0, s2>>>(hidden);
    cudaEventRecord(evC, s2);                       // att done

    // s0: cheb chain (needs build_x0)
    cudaStreamWaitEvent(s0, evA, 0);
    dim3 gC(8, BSZ);
    k_cheb_mma<<<gC, 512, CB_SMEM, s0>>>(0);
    cudaEventRecord(ev1, s0);                       // x1 ready
    k_cheb_mma<<<gC, 512, CB_SMEM, s0>>>(1);
    cudaEventRecord(ev2, s0);                       // x2 ready
    k_cheb_mma<<<gC, 512, CB_SMEM, s0>>>(2);        // -> x3

    // s1: gemm2 partials as inputs become available
    k_gemm2_mma<<<128, 256, G2_SMEM, s1>>>(0);
    cudaStreamWaitEvent(s1, ev1, 0);
    k_gemm2_mma<<<128, 256, G2_SMEM, s1>>>(1);
    cudaStreamWaitEvent(s1, ev2, 0);
    k_gemm2_mma<<<128, 256, G2_SMEM, s1>>>(2);
    cudaEventRecord(evG, s1);

    // s0: last partial, then final
    k_gemm2_mma<<<128, 256, G2_SMEM, s0>>>(3);
    cudaStreamWaitEvent(s0, evG, 0);
    cudaStreamWaitEvent(s0, evC, 0);
    k_final<<<(BSZ * NN) / 64, 256, 0, s0>>>(W, bias, gc_b, out);
}